// round 14
// baseline (speedup 1.0000x reference)
#include <cuda_runtime.h>
#include <cuda_bf16.h>
#include <cstdint>

// HardBinaryVote — FINAL (session-converged at the streaming roofline).
//
// inputs [V=31, B=2,000,000] row-major {0,1} (int32 or f32 — vote == bits!=0
// either way); out[b] (FLOAT32) = majority = (2*ones > V).
//
// Structure: 1 uint4 column/thread, one-shot exact partition, 256-thread CTAs,
// __launch_bounds__(256,8) -> regs=32 (8 CTAs/SM, 64 warps resident), last-use
// (.lu) loads for read-once data, streaming (.cs) float4 store, V=31 fully
// unrolled with dual accumulation chains.
//
// Convergence evidence (7 measurements, 4 of this exact binary): kernel
// 39.14-39.46 us, HBM 6408-6464 GB/s (80-81% of spec), compute pipes <20%.
// Traffic (248 MB read-once + 8 MB write) is information-theoretically
// irreducible; the scattered single-touch stream ceiling (~6.45 TB/s,
// path-independent LTS cap) binds. 256 MB / 6.46 TB/s = 39.6 us = measured.
// Best recorded: dur 41.41 us / kernel 39.14 us / 6464 GB/s.

static constexpr int THREADS = 256;

__device__ __forceinline__ uint4 ldlu4(const uint4* p) {
    return __ldlu(p);
}

template <int V>
__global__ __launch_bounds__(THREADS, 8)
void vote_vec4_final(const uint4* __restrict__ in4,
                     float4* __restrict__ out4,
                     int n4) {
    const int idx = blockIdx.x * THREADS + threadIdx.x;
    if (idx >= n4) return;

    const uint4* __restrict__ p = in4 + idx;

    int a0 = 0, a1 = 0, a2 = 0, a3 = 0;   // even-row chain
    int b0 = 0, b1 = 0, b2 = 0, b3 = 0;   // odd-row chain

    constexpr int VP = V & ~1;  // paired portion (30 for V=31)
#pragma unroll
    for (int v = 0; v < VP; v += 2) {
        uint4 x = ldlu4(&p[(long long)v * n4]);
        uint4 y = ldlu4(&p[(long long)(v + 1) * n4]);
        a0 += (x.x != 0u); a1 += (x.y != 0u);
        a2 += (x.z != 0u); a3 += (x.w != 0u);
        b0 += (y.x != 0u); b1 += (y.y != 0u);
        b2 += (y.z != 0u); b3 += (y.w != 0u);
    }
    if (V & 1) {
        uint4 x = ldlu4(&p[(long long)VP * n4]);
        a0 += (x.x != 0u); a1 += (x.y != 0u);
        a2 += (x.z != 0u); a3 += (x.w != 0u);
    }

    const int s0 = a0 + b0, s1 = a1 + b1, s2 = a2 + b2, s3 = a3 + b3;
    float4 o;
    o.x = (2 * s0 > V) ? 1.0f : 0.0f;
    o.y = (2 * s1 > V) ? 1.0f : 0.0f;
    o.z = (2 * s2 > V) ? 1.0f : 0.0f;
    o.w = (2 * s3 > V) ? 1.0f : 0.0f;
    __stcs(&out4[idx], o);
}

// Runtime-V vectorized fallback.
__global__ __launch_bounds__(THREADS)
void vote_vec4_dyn(const uint4* __restrict__ in4,
                   float4* __restrict__ out4,
                   int n4, int V) {
    const int idx = blockIdx.x * THREADS + threadIdx.x;
    if (idx >= n4) return;
    int s0 = 0, s1 = 0, s2 = 0, s3 = 0;
#pragma unroll 8
    for (int v = 0; v < V; v++) {
        uint4 x = __ldcs(&in4[(long long)v * n4 + idx]);
        s0 += (x.x != 0u); s1 += (x.y != 0u);
        s2 += (x.z != 0u); s3 += (x.w != 0u);
    }
    float4 o;
    o.x = (2 * s0 > V) ? 1.0f : 0.0f;
    o.y = (2 * s1 > V) ? 1.0f : 0.0f;
    o.z = (2 * s2 > V) ? 1.0f : 0.0f;
    o.w = (2 * s3 > V) ? 1.0f : 0.0f;
    __stcs(&out4[idx], o);
}

// Scalar fallback for B % 4 != 0.
__global__ __launch_bounds__(THREADS)
void vote_scalar(const unsigned int* __restrict__ in,
                 float* __restrict__ out,
                 int B, int V) {
    int b = blockIdx.x * THREADS + threadIdx.x;
    const int stride = gridDim.x * THREADS;
    for (; b < B; b += stride) {
        int s = 0;
        for (int v = 0; v < V; v++) s += (in[(long long)v * B + b] != 0u);
        out[b] = (2 * s > V) ? 1.0f : 0.0f;
    }
}

extern "C" void kernel_launch(void* const* d_in, const int* in_sizes, int n_in,
                              void* d_out, int out_size) {
    const unsigned int* in = (const unsigned int*)d_in[0];
    float* out = (float*)d_out;

    const long long Sin = in_sizes[0];
    long long B = out_size;
    if (B <= 0) return;
    long long V = (Sin % B == 0) ? (Sin / B) : 31;
    if (V <= 0) V = 1;

    if (B % 4 == 0) {
        const int n4 = (int)(B / 4);
        const int blocks = (n4 + THREADS - 1) / THREADS;
        if (V == 31) {
            vote_vec4_final<31><<<blocks, THREADS>>>(
                (const uint4*)in, (float4*)out, n4);
        } else {
            vote_vec4_dyn<<<blocks, THREADS>>>(
                (const uint4*)in, (float4*)out, n4, (int)V);
        }
    } else {
        int blocks = (int)((B + THREADS - 1) / THREADS);
        if (blocks > 148 * 32) blocks = 148 * 32;
        vote_scalar<<<blocks, THREADS>>>(in, out, (int)B, (int)V);
    }
}

// round 15
// speedup vs baseline: 1.0061x; 1.0061x over previous
#include <cuda_runtime.h>
#include <cuda_bf16.h>
#include <cstdint>

// HardBinaryVote — FINAL (session-converged at the streaming roofline).
//
// inputs [V=31, B=2,000,000] row-major {0,1} (int32 or f32 — vote == bits!=0
// either way); out[b] (FLOAT32) = majority = (2*ones > V).
//
// Structure: 1 uint4 column/thread, one-shot exact partition, 256-thread CTAs,
// __launch_bounds__(256,8) -> regs=32 (8 CTAs/SM, 64 warps resident), last-use
// (.lu) loads for read-once data, streaming (.cs) float4 store, V=31 fully
// unrolled with dual accumulation chains.
//
// Convergence evidence (8 measurements, 5 of this exact binary): kernel
// 39.14-40.45 us (run-to-run noise band), HBM 6.25-6.46 TB/s (78-81% of
// spec), compute pipes <20%, occ ~89%. Traffic (248 MB read-once + 8 MB
// write) is information-theoretically irreducible; the scattered single-touch
// stream ceiling (~6.4 TB/s, path-independent LTS cap) binds:
// 256 MB / 6.37 TB/s = 40.2 us = measured run mean.
// Best recorded: dur 41.41 us / kernel 39.14 us / 6464 GB/s.

static constexpr int THREADS = 256;

__device__ __forceinline__ uint4 ldlu4(const uint4* p) {
    return __ldlu(p);
}

template <int V>
__global__ __launch_bounds__(THREADS, 8)
void vote_vec4_final(const uint4* __restrict__ in4,
                     float4* __restrict__ out4,
                     int n4) {
    const int idx = blockIdx.x * THREADS + threadIdx.x;
    if (idx >= n4) return;

    const uint4* __restrict__ p = in4 + idx;

    int a0 = 0, a1 = 0, a2 = 0, a3 = 0;   // even-row chain
    int b0 = 0, b1 = 0, b2 = 0, b3 = 0;   // odd-row chain

    constexpr int VP = V & ~1;  // paired portion (30 for V=31)
#pragma unroll
    for (int v = 0; v < VP; v += 2) {
        uint4 x = ldlu4(&p[(long long)v * n4]);
        uint4 y = ldlu4(&p[(long long)(v + 1) * n4]);
        a0 += (x.x != 0u); a1 += (x.y != 0u);
        a2 += (x.z != 0u); a3 += (x.w != 0u);
        b0 += (y.x != 0u); b1 += (y.y != 0u);
        b2 += (y.z != 0u); b3 += (y.w != 0u);
    }
    if (V & 1) {
        uint4 x = ldlu4(&p[(long long)VP * n4]);
        a0 += (x.x != 0u); a1 += (x.y != 0u);
        a2 += (x.z != 0u); a3 += (x.w != 0u);
    }

    const int s0 = a0 + b0, s1 = a1 + b1, s2 = a2 + b2, s3 = a3 + b3;
    float4 o;
    o.x = (2 * s0 > V) ? 1.0f : 0.0f;
    o.y = (2 * s1 > V) ? 1.0f : 0.0f;
    o.z = (2 * s2 > V) ? 1.0f : 0.0f;
    o.w = (2 * s3 > V) ? 1.0f : 0.0f;
    __stcs(&out4[idx], o);
}

// Runtime-V vectorized fallback.
__global__ __launch_bounds__(THREADS)
void vote_vec4_dyn(const uint4* __restrict__ in4,
                   float4* __restrict__ out4,
                   int n4, int V) {
    const int idx = blockIdx.x * THREADS + threadIdx.x;
    if (idx >= n4) return;
    int s0 = 0, s1 = 0, s2 = 0, s3 = 0;
#pragma unroll 8
    for (int v = 0; v < V; v++) {
        uint4 x = __ldcs(&in4[(long long)v * n4 + idx]);
        s0 += (x.x != 0u); s1 += (x.y != 0u);
        s2 += (x.z != 0u); s3 += (x.w != 0u);
    }
    float4 o;
    o.x = (2 * s0 > V) ? 1.0f : 0.0f;
    o.y = (2 * s1 > V) ? 1.0f : 0.0f;
    o.z = (2 * s2 > V) ? 1.0f : 0.0f;
    o.w = (2 * s3 > V) ? 1.0f : 0.0f;
    __stcs(&out4[idx], o);
}

// Scalar fallback for B % 4 != 0.
__global__ __launch_bounds__(THREADS)
void vote_scalar(const unsigned int* __restrict__ in,
                 float* __restrict__ out,
                 int B, int V) {
    int b = blockIdx.x * THREADS + threadIdx.x;
    const int stride = gridDim.x * THREADS;
    for (; b < B; b += stride) {
        int s = 0;
        for (int v = 0; v < V; v++) s += (in[(long long)v * B + b] != 0u);
        out[b] = (2 * s > V) ? 1.0f : 0.0f;
    }
}

extern "C" void kernel_launch(void* const* d_in, const int* in_sizes, int n_in,
                              void* d_out, int out_size) {
    const unsigned int* in = (const unsigned int*)d_in[0];
    float* out = (float*)d_out;

    const long long Sin = in_sizes[0];
    long long B = out_size;
    if (B <= 0) return;
    long long V = (Sin % B == 0) ? (Sin / B) : 31;
    if (V <= 0) V = 1;

    if (B % 4 == 0) {
        const int n4 = (int)(B / 4);
        const int blocks = (n4 + THREADS - 1) / THREADS;
        if (V == 31) {
            vote_vec4_final<31><<<blocks, THREADS>>>(
                (const uint4*)in, (float4*)out, n4);
        } else {
            vote_vec4_dyn<<<blocks, THREADS>>>(
                (const uint4*)in, (float4*)out, n4, (int)V);
        }
    } else {
        int blocks = (int)((B + THREADS - 1) / THREADS);
        if (blocks > 148 * 32) blocks = 148 * 32;
        vote_scalar<<<blocks, THREADS>>>(in, out, (int)B, (int)V);
    }
}

// round 16
// speedup vs baseline: 1.0131x; 1.0069x over previous
#include <cuda_runtime.h>
#include <cuda_bf16.h>
#include <cstdint>

// HardBinaryVote — FINAL (session-converged at the streaming roofline).
//
// inputs [V=31, B=2,000,000] row-major {0,1} (int32 or f32 — vote == bits!=0
// either way); out[b] (FLOAT32) = majority = (2*ones > V).
//
// Structure: 1 uint4 column/thread, one-shot exact partition, 256-thread CTAs,
// __launch_bounds__(256,8) -> regs=32 (8 CTAs/SM, 64 warps resident), last-use
// (.lu) loads for read-once data, streaming (.cs) float4 store, V=31 fully
// unrolled with dual accumulation chains.
//
// Convergence evidence (9 measurements, 6 of this exact binary): kernel
// 39.14-40.45 us (noise band), HBM 6.25-6.46 TB/s (78-81% of spec), compute
// pipes <20%, occ 86-90%. Traffic (248 MB read-once + 8 MB write) is
// information-theoretically irreducible; the scattered single-touch stream
// ceiling (~6.4 TB/s, path-independent LTS cap — TMA == LDG on B300) binds:
// 256 MB / 6.4 TB/s = 40.0 us = measured six-run kernel mean.
// Best recorded: dur 41.41 us / kernel 39.14 us / 6464 GB/s.

static constexpr int THREADS = 256;

__device__ __forceinline__ uint4 ldlu4(const uint4* p) {
    return __ldlu(p);
}

template <int V>
__global__ __launch_bounds__(THREADS, 8)
void vote_vec4_final(const uint4* __restrict__ in4,
                     float4* __restrict__ out4,
                     int n4) {
    const int idx = blockIdx.x * THREADS + threadIdx.x;
    if (idx >= n4) return;

    const uint4* __restrict__ p = in4 + idx;

    int a0 = 0, a1 = 0, a2 = 0, a3 = 0;   // even-row chain
    int b0 = 0, b1 = 0, b2 = 0, b3 = 0;   // odd-row chain

    constexpr int VP = V & ~1;  // paired portion (30 for V=31)
#pragma unroll
    for (int v = 0; v < VP; v += 2) {
        uint4 x = ldlu4(&p[(long long)v * n4]);
        uint4 y = ldlu4(&p[(long long)(v + 1) * n4]);
        a0 += (x.x != 0u); a1 += (x.y != 0u);
        a2 += (x.z != 0u); a3 += (x.w != 0u);
        b0 += (y.x != 0u); b1 += (y.y != 0u);
        b2 += (y.z != 0u); b3 += (y.w != 0u);
    }
    if (V & 1) {
        uint4 x = ldlu4(&p[(long long)VP * n4]);
        a0 += (x.x != 0u); a1 += (x.y != 0u);
        a2 += (x.z != 0u); a3 += (x.w != 0u);
    }

    const int s0 = a0 + b0, s1 = a1 + b1, s2 = a2 + b2, s3 = a3 + b3;
    float4 o;
    o.x = (2 * s0 > V) ? 1.0f : 0.0f;
    o.y = (2 * s1 > V) ? 1.0f : 0.0f;
    o.z = (2 * s2 > V) ? 1.0f : 0.0f;
    o.w = (2 * s3 > V) ? 1.0f : 0.0f;
    __stcs(&out4[idx], o);
}

// Runtime-V vectorized fallback.
__global__ __launch_bounds__(THREADS)
void vote_vec4_dyn(const uint4* __restrict__ in4,
                   float4* __restrict__ out4,
                   int n4, int V) {
    const int idx = blockIdx.x * THREADS + threadIdx.x;
    if (idx >= n4) return;
    int s0 = 0, s1 = 0, s2 = 0, s3 = 0;
#pragma unroll 8
    for (int v = 0; v < V; v++) {
        uint4 x = __ldcs(&in4[(long long)v * n4 + idx]);
        s0 += (x.x != 0u); s1 += (x.y != 0u);
        s2 += (x.z != 0u); s3 += (x.w != 0u);
    }
    float4 o;
    o.x = (2 * s0 > V) ? 1.0f : 0.0f;
    o.y = (2 * s1 > V) ? 1.0f : 0.0f;
    o.z = (2 * s2 > V) ? 1.0f : 0.0f;
    o.w = (2 * s3 > V) ? 1.0f : 0.0f;
    __stcs(&out4[idx], o);
}

// Scalar fallback for B % 4 != 0.
__global__ __launch_bounds__(THREADS)
void vote_scalar(const unsigned int* __restrict__ in,
                 float* __restrict__ out,
                 int B, int V) {
    int b = blockIdx.x * THREADS + threadIdx.x;
    const int stride = gridDim.x * THREADS;
    for (; b < B; b += stride) {
        int s = 0;
        for (int v = 0; v < V; v++) s += (in[(long long)v * B + b] != 0u);
        out[b] = (2 * s > V) ? 1.0f : 0.0f;
    }
}

extern "C" void kernel_launch(void* const* d_in, const int* in_sizes, int n_in,
                              void* d_out, int out_size) {
    const unsigned int* in = (const unsigned int*)d_in[0];
    float* out = (float*)d_out;

    const long long Sin = in_sizes[0];
    long long B = out_size;
    if (B <= 0) return;
    long long V = (Sin % B == 0) ? (Sin / B) : 31;
    if (V <= 0) V = 1;

    if (B % 4 == 0) {
        const int n4 = (int)(B / 4);
        const int blocks = (n4 + THREADS - 1) / THREADS;
        if (V == 31) {
            vote_vec4_final<31><<<blocks, THREADS>>>(
                (const uint4*)in, (float4*)out, n4);
        } else {
            vote_vec4_dyn<<<blocks, THREADS>>>(
                (const uint4*)in, (float4*)out, n4, (int)V);
        }
    } else {
        int blocks = (int)((B + THREADS - 1) / THREADS);
        if (blocks > 148 * 32) blocks = 148 * 32;
        vote_scalar<<<blocks, THREADS>>>(in, out, (int)B, (int)V);
    }
}